// round 2
// baseline (speedup 1.0000x reference)
#include <cuda_runtime.h>
#include <cstdint>

// compressor_17454747091102: 8-voter bitwise majority.
// out[j] bit i of packed word = 1 iff >=5 of the 8 input words src[v][j] have
// bit i set (sign-sum < 0; tie at 4/4 -> nonnegative -> bit clear).
// Harness output dtype is float32: store (float)(int32)packed_word.

__device__ __forceinline__ void fa(uint32_t a, uint32_t b, uint32_t c,
                                   uint32_t& s, uint32_t& cy) {
    s  = a ^ b ^ c;
    cy = (a & b) | (c & (a ^ b));   // majority -> single LOP3
}

__device__ __forceinline__ uint32_t maj8(uint32_t w0, uint32_t w1, uint32_t w2,
                                         uint32_t w3, uint32_t w4, uint32_t w5,
                                         uint32_t w6, uint32_t w7) {
    uint32_t sa, ca, sb, cb;
    fa(w0, w1, w2, sa, ca);          // weight1: sa, weight2: ca
    fa(w3, w4, w5, sb, cb);
    uint32_t sc = w6 ^ w7;           // half adder
    uint32_t cc = w6 & w7;

    uint32_t S0, cd;
    fa(sa, sb, sc, S0, cd);          // weight1: S0, weight2: cd

    uint32_t s1p, ce;
    fa(ca, cb, cc, s1p, ce);         // weight2: s1p, weight4: ce

    uint32_t S1 = s1p ^ cd;          // weight2
    uint32_t cf = s1p & cd;          // weight4

    uint32_t S2 = ce ^ cf;           // weight4
    uint32_t S3 = ce & cf;           // weight8

    // popcount = S0 + 2*S1 + 4*S2 + 8*S3 ; set iff >= 5
    return S3 | (S2 & (S1 | S0));
}

__global__ void __launch_bounds__(256)
majority_vote_kernel(const int4* __restrict__ src, float4* __restrict__ out, int m4) {
    int idx = blockIdx.x * blockDim.x + threadIdx.x;
    if (idx >= m4) return;

    // Front-batched independent 128-bit loads: MLP = 8
    int4 v0 = src[0 * m4 + idx];
    int4 v1 = src[1 * m4 + idx];
    int4 v2 = src[2 * m4 + idx];
    int4 v3 = src[3 * m4 + idx];
    int4 v4 = src[4 * m4 + idx];
    int4 v5 = src[5 * m4 + idx];
    int4 v6 = src[6 * m4 + idx];
    int4 v7 = src[7 * m4 + idx];

    int rx = (int)maj8((uint32_t)v0.x, (uint32_t)v1.x, (uint32_t)v2.x, (uint32_t)v3.x,
                       (uint32_t)v4.x, (uint32_t)v5.x, (uint32_t)v6.x, (uint32_t)v7.x);
    int ry = (int)maj8((uint32_t)v0.y, (uint32_t)v1.y, (uint32_t)v2.y, (uint32_t)v3.y,
                       (uint32_t)v4.y, (uint32_t)v5.y, (uint32_t)v6.y, (uint32_t)v7.y);
    int rz = (int)maj8((uint32_t)v0.z, (uint32_t)v1.z, (uint32_t)v2.z, (uint32_t)v3.z,
                       (uint32_t)v4.z, (uint32_t)v5.z, (uint32_t)v6.z, (uint32_t)v7.z);
    int rw = (int)maj8((uint32_t)v0.w, (uint32_t)v1.w, (uint32_t)v2.w, (uint32_t)v3.w,
                       (uint32_t)v4.w, (uint32_t)v5.w, (uint32_t)v6.w, (uint32_t)v7.w);

    float4 r;
    r.x = __int2float_rn(rx);
    r.y = __int2float_rn(ry);
    r.z = __int2float_rn(rz);
    r.w = __int2float_rn(rw);
    out[idx] = r;
}

extern "C" void kernel_launch(void* const* d_in, const int* in_sizes, int n_in,
                              void* d_out, int out_size) {
    // d_in[0] = para_temp (float, 1 elem), d_in[1] = src (8*M int32).
    // Robust: pick the larger input as src.
    const int* src = (const int*)d_in[1];
    long long n_src = in_sizes[1];
    if (n_in > 1 && in_sizes[0] > in_sizes[1]) { src = (const int*)d_in[0]; n_src = in_sizes[0]; }

    int M  = (int)(n_src / 8);     // packed words per voter == out_size
    int m4 = M / 4;                // int4 chunks

    int threads = 256;
    int blocks  = (m4 + threads - 1) / threads;
    majority_vote_kernel<<<blocks, threads>>>((const int4*)src, (float4*)d_out, m4);
}